// round 1
// baseline (speedup 1.0000x reference)
#include <cuda_runtime.h>

#define NMAX   500000
#define DIN    256
#define DHID   128
#define NHEADS 4
#define DOUT   4

// ---- persistent scratch (no allocations allowed) ----
__device__ int g_rowidx[NMAX];
__device__ int g_counts[NHEADS];
__device__ int g_offsets[NHEADS];
__device__ int g_cursor[NHEADS];

// ---- packed f32x2 helpers (Blackwell FFMA2, only reachable via PTX) ----
__device__ __forceinline__ unsigned long long ffma2(unsigned long long a,
                                                    unsigned long long b,
                                                    unsigned long long c) {
    unsigned long long d;
    asm("fma.rn.f32x2 %0, %1, %2, %3;" : "=l"(d) : "l"(a), "l"(b), "l"(c));
    return d;
}
__device__ __forceinline__ float2 unpack2(unsigned long long v) {
    float2 r;
    asm("mov.b64 {%0, %1}, %2;" : "=f"(r.x), "=f"(r.y) : "l"(v));
    return r;
}

// ============================================================
// Pass 0: zero the head counters
// ============================================================
__global__ void zero_kernel() {
    int t = threadIdx.x;
    if (t < NHEADS) g_counts[t] = 0;
}

// ============================================================
// Pass 1: histogram of heads
// ============================================================
__global__ void hist_kernel(const int* __restrict__ heads, int n) {
    __shared__ int sc[NHEADS];
    int t = threadIdx.x;
    if (t < NHEADS) sc[t] = 0;
    __syncthreads();
    int i = blockIdx.x * (blockDim.x * 4) + t;
    #pragma unroll
    for (int u = 0; u < 4; ++u, i += blockDim.x)
        if (i < n) atomicAdd(&sc[heads[i]], 1);
    __syncthreads();
    if (t < NHEADS) atomicAdd(&g_counts[t], sc[t]);
}

// ============================================================
// Pass 2: tiny exclusive scan (4 bins)
// ============================================================
__global__ void scan_kernel() {
    if (threadIdx.x == 0 && blockIdx.x == 0) {
        int off = 0;
        #pragma unroll
        for (int h = 0; h < NHEADS; ++h) {
            g_offsets[h] = off;
            g_cursor[h]  = off;
            off += g_counts[h];
        }
    }
}

// ============================================================
// Pass 3: scatter row indices into bins (CTA-aggregated atomics)
// ============================================================
__global__ void scatter_kernel(const int* __restrict__ heads, int n) {
    __shared__ int scount[NHEADS];
    __shared__ int sbase[NHEADS];
    __shared__ int scur[NHEADS];
    int t = threadIdx.x;
    if (t < NHEADS) scount[t] = 0;
    __syncthreads();

    int base = blockIdx.x * 1024;
    int h[4], idx[4];
    #pragma unroll
    for (int u = 0; u < 4; ++u) {
        int i = base + t + u * 256;
        idx[u] = i;
        if (i < n) { h[u] = heads[i]; atomicAdd(&scount[h[u]], 1); }
        else         h[u] = -1;
    }
    __syncthreads();
    if (t < NHEADS) {
        sbase[t] = atomicAdd(&g_cursor[t], scount[t]);
        scur[t]  = 0;
    }
    __syncthreads();
    #pragma unroll
    for (int u = 0; u < 4; ++u) {
        if (h[u] >= 0) {
            int lp = atomicAdd(&scur[h[u]], 1);
            g_rowidx[sbase[h[u]] + lp] = idx[u];
        }
    }
}

// ============================================================
// Pass 4: fused masked-MLP compute
//   CTA = (chunk of 1024 rows) x (head). 8 warps, 16 rows/warp/iter.
//   W1 head-block transposed + duplicated {w,w} in smem (stride-padded),
//   x staged as interleaved row-pairs so LDS.128 feeds FFMA2 directly.
// ============================================================
#define WARPS         8
#define ROWS_PER_WARP 16           // 8 f32x2 row pairs
#define ROWS_PER_ITER (WARPS * ROWS_PER_WARP)   // 128
#define CHUNK_ITERS   8
#define CHUNK         (ROWS_PER_ITER * CHUNK_ITERS)  // 1024
#define W1_STRIDE     516          // 512 duplicated floats + 4 pad (stride % 32 == 4)
#define XBUF_FLOATS   4096         // 8 pairs * 512 floats
#define SMEM_FLOATS   (32 * W1_STRIDE + WARPS * XBUF_FLOATS)
#define SMEM_BYTES    (SMEM_FLOATS * 4)

__global__ void __launch_bounds__(256, 1)
compute_kernel(const float* __restrict__ x, const float* __restrict__ W1,
               const float* __restrict__ W2, float* __restrict__ out, int n) {
    const int head = blockIdx.y;
    const int cnt  = g_counts[head];
    const int chunk_base = blockIdx.x * CHUNK;
    if (chunk_base >= cnt) return;
    const int binstart = g_offsets[head];

    extern __shared__ float smem[];
    float* w1d = smem;                       // 32 * 516 floats (66 KB)
    float* xb  = smem + 32 * W1_STRIDE;      // 8 warps * 4096 floats (128 KB)

    const int tid  = threadIdx.x;
    const int warp = tid >> 5;
    const int lane = tid & 31;

    // ---- load W1 block for this head: transposed + duplicated {w,w} ----
    for (int idx = tid; idx < 32 * DIN; idx += 256) {
        int j = idx & 31;          // hidden col within block (coalesced gmem read)
        int k = idx >> 5;          // input dim
        float w = W1[k * DHID + head * 32 + j];
        *reinterpret_cast<float2*>(&w1d[j * W1_STRIDE + 2 * k]) = make_float2(w, w);
    }

    // ---- preload this lane's W2 output-column into registers ----
    const int myo   = lane & 3;    // output channel
    const int myrow = lane >> 2;   // local row slot (0..7)
    float w2col[32];
    #pragma unroll
    for (int j = 0; j < 32; ++j)
        w2col[j] = W2[(head * 32 + j) * DOUT + myo];

    __syncthreads();

    float* xw = xb + warp * XBUF_FLOATS;

    const float S1 = 0.0625f;                 // 1/sqrt(256)
    const float S2 = 0.08838834764831845f;    // 1/sqrt(128)

    for (int it = 0; it < CHUNK_ITERS; ++it) {
        const int g0 = chunk_base + it * ROWS_PER_ITER + warp * ROWS_PER_WARP;
        if (g0 >= cnt) break;                  // warp-uniform

        // ---- stage 16 rows as 8 interleaved pairs ----
        #pragma unroll
        for (int p = 0; p < 8; ++p) {
            int ga = g0 + 2 * p, gb = g0 + 2 * p + 1;
            int r0 = g_rowidx[binstart + ((ga < cnt) ? ga : 0)];
            int r1 = g_rowidx[binstart + ((gb < cnt) ? gb : 0)];
            const float4* xr0 = reinterpret_cast<const float4*>(x + r0 * DIN);
            const float4* xr1 = reinterpret_cast<const float4*>(x + r1 * DIN);
            #pragma unroll
            for (int u = 0; u < 2; ++u) {
                float4 a = xr0[u * 32 + lane];
                float4 b = xr1[u * 32 + lane];
                int m0 = u * 64 + lane * 2;   // k-pair group index
                *reinterpret_cast<float4*>(&xw[p * 512 + m0 * 4]) =
                    make_float4(a.x, b.x, a.y, b.y);
                *reinterpret_cast<float4*>(&xw[p * 512 + m0 * 4 + 4]) =
                    make_float4(a.z, b.z, a.w, b.w);
            }
        }
        __syncwarp();

        // ---- main loop: h[j] for 16 rows via packed FFMA2 ----
        unsigned long long acc[8];
        #pragma unroll
        for (int p = 0; p < 8; ++p) acc[p] = 0ULL;

        const ulonglong2* wptr =
            reinterpret_cast<const ulonglong2*>(&w1d[lane * W1_STRIDE]);
        #pragma unroll 4
        for (int k2 = 0; k2 < 128; ++k2) {
            ulonglong2 wv = wptr[k2];   // {w_k,w_k},{w_k1,w_k1}
            #pragma unroll
            for (int p = 0; p < 8; ++p) {
                ulonglong2 xv =
                    *reinterpret_cast<const ulonglong2*>(&xw[p * 512 + k2 * 4]);
                acc[p] = ffma2(wv.x, xv.x, acc[p]);
                acc[p] = ffma2(wv.y, xv.y, acc[p]);
            }
        }
        __syncwarp();

        // ---- silu + transpose through smem scratch (reuse xw) ----
        float* sb = xw;   // 32 lanes * stride 20 floats
        #pragma unroll
        for (int p = 0; p < 8; ++p) {
            float2 v = unpack2(acc[p]);
            v.x *= S1; v.y *= S1;
            v.x = __fdividef(v.x, 1.0f + __expf(-v.x));
            v.y = __fdividef(v.y, 1.0f + __expf(-v.y));
            *reinterpret_cast<float2*>(&sb[lane * 20 + 2 * p]) = v;
        }
        __syncwarp();

        // ---- second matmul: lane owns (row, out-col); W2 col in registers ----
        float o0 = 0.f, o1 = 0.f;
        #pragma unroll
        for (int j = 0; j < 32; ++j) {
            o0 = fmaf(sb[j * 20 + myrow],     w2col[j], o0);
            o1 = fmaf(sb[j * 20 + myrow + 8], w2col[j], o1);
        }
        o0 *= S2; o1 *= S2;

        int gq0 = g0 + myrow, gq1 = g0 + myrow + 8;
        if (gq0 < cnt) out[g_rowidx[binstart + gq0] * DOUT + myo] = o0;
        if (gq1 < cnt) out[g_rowidx[binstart + gq1] * DOUT + myo] = o1;
        __syncwarp();   // before next iter reuses xw
    }
}

// ============================================================
// launcher
// ============================================================
extern "C" void kernel_launch(void* const* d_in, const int* in_sizes, int n_in,
                              void* d_out, int out_size) {
    const float* x     = (const float*)d_in[0];
    const float* W1    = (const float*)d_in[1];
    const float* W2    = (const float*)d_in[2];
    const int*   heads = (const int*)d_in[3];
    float*       out   = (float*)d_out;

    int n = in_sizes[0] / DIN;
    if (n > NMAX) n = NMAX;
    if (n <= 0) return;

    static int attr_done = 0;   // host-side API config, not device work
    if (!attr_done) {
        cudaFuncSetAttribute(compute_kernel,
                             cudaFuncAttributeMaxDynamicSharedMemorySize,
                             SMEM_BYTES);
        attr_done = 1;
    }

    zero_kernel<<<1, 32>>>();
    int hist_blocks = (n + 1023) / 1024;
    hist_kernel<<<hist_blocks, 256>>>(heads, n);
    scan_kernel<<<1, 32>>>();
    scatter_kernel<<<hist_blocks, 256>>>(heads, n);

    dim3 grid((n + CHUNK - 1) / CHUNK, NHEADS);
    compute_kernel<<<grid, 256, SMEM_BYTES>>>(x, W1, W2, out, n);
}

// round 2
// speedup vs baseline: 1.1475x; 1.1475x over previous
#include <cuda_runtime.h>
#include <cstdint>

#define NMAX   500000
#define DIN    256
#define DHID   128
#define NHEADS 4
#define DOUT   4

// ---- persistent scratch (no allocations allowed) ----
__device__ int g_rowidx[NMAX];
__device__ int g_counts[NHEADS];
__device__ int g_offsets[NHEADS];
__device__ int g_cursor[NHEADS];

// ---- packed f32x2 FFMA2 (Blackwell, PTX-only) ----
__device__ __forceinline__ unsigned long long ffma2(unsigned long long a,
                                                    unsigned long long b,
                                                    unsigned long long c) {
    unsigned long long d;
    asm("fma.rn.f32x2 %0, %1, %2, %3;" : "=l"(d) : "l"(a), "l"(b), "l"(c));
    return d;
}
__device__ __forceinline__ float2 unpack2(unsigned long long v) {
    float2 r;
    asm("mov.b64 {%0, %1}, %2;" : "=f"(r.x), "=f"(r.y) : "l"(v));
    return r;
}

// ---- cp.async helpers ----
__device__ __forceinline__ void cpasync16(uint32_t saddr, const void* gaddr) {
    asm volatile("cp.async.cg.shared.global [%0], [%1], 16;"
                 :: "r"(saddr), "l"(gaddr));
}
#define CP_COMMIT()   asm volatile("cp.async.commit_group;" ::: "memory")
#define CP_WAIT1()    asm volatile("cp.async.wait_group 1;" ::: "memory")
#define CP_WAIT_ALL() asm volatile("cp.async.wait_all;"     ::: "memory")

// ============================================================
// Binning passes (cheap: ~15us total)
// ============================================================
__global__ void zero_kernel() {
    int t = threadIdx.x;
    if (t < NHEADS) g_counts[t] = 0;
}

__global__ void hist_kernel(const int* __restrict__ heads, int n) {
    __shared__ int sc[NHEADS];
    int t = threadIdx.x;
    if (t < NHEADS) sc[t] = 0;
    __syncthreads();
    int i = blockIdx.x * (blockDim.x * 4) + t;
    #pragma unroll
    for (int u = 0; u < 4; ++u, i += blockDim.x)
        if (i < n) atomicAdd(&sc[heads[i]], 1);
    __syncthreads();
    if (t < NHEADS) atomicAdd(&g_counts[t], sc[t]);
}

__global__ void scan_kernel() {
    if (threadIdx.x == 0 && blockIdx.x == 0) {
        int off = 0;
        #pragma unroll
        for (int h = 0; h < NHEADS; ++h) {
            g_offsets[h] = off;
            g_cursor[h]  = off;
            off += g_counts[h];
        }
    }
}

__global__ void scatter_kernel(const int* __restrict__ heads, int n) {
    __shared__ int scount[NHEADS];
    __shared__ int sbase[NHEADS];
    __shared__ int scur[NHEADS];
    int t = threadIdx.x;
    if (t < NHEADS) scount[t] = 0;
    __syncthreads();

    int base = blockIdx.x * 1024;
    int h[4], idx[4];
    #pragma unroll
    for (int u = 0; u < 4; ++u) {
        int i = base + t + u * 256;
        idx[u] = i;
        if (i < n) { h[u] = heads[i]; atomicAdd(&scount[h[u]], 1); }
        else         h[u] = -1;
    }
    __syncthreads();
    if (t < NHEADS) {
        sbase[t] = atomicAdd(&g_cursor[t], scount[t]);
        scur[t]  = 0;
    }
    __syncthreads();
    #pragma unroll
    for (int u = 0; u < 4; ++u) {
        if (h[u] >= 0) {
            int lp = atomicAdd(&scur[h[u]], 1);
            g_rowidx[sbase[h[u]] + lp] = idx[u];
        }
    }
}

// ============================================================
// Fused compute: K-paired FFMA2 + cp.async double-buffered x
//   CTA = (chunk of 512 rows) x head. 8 warps, 8 rows/warp/iter.
//   lane = hidden channel j (0..31); acc{even-k, odd-k} per row.
//   x staged row-major verbatim via cp.async (16B/lane), 2 buffers.
// ============================================================
#define WARPS      8
#define RPW        8                      // rows per warp per iter
#define ROWS_ITER  (WARPS * RPW)          // 64
#define ITERS      8
#define CHUNK      (ROWS_ITER * ITERS)    // 512
#define WSTRIDE    260                    // 256 + 4 pad -> conflict-free LDS.128
#define WSMEM      (32 * WSTRIDE)         // 8320 floats
#define XBUF       (RPW * DIN)            // 2048 floats per buffer
#define SCRW       288                    // 32*9 scratch floats per warp
#define SMEM_FLOATS (WSMEM + WARPS * 2 * XBUF + WARPS * SCRW + 128)
#define SMEM_BYTES  (SMEM_FLOATS * 4)     // ~174 KB

__device__ __forceinline__ void stage_rows(float* __restrict__ xb,
                                           const float* __restrict__ x,
                                           const int* __restrict__ rbin,
                                           int g0, int cnt, int lane) {
    #pragma unroll
    for (int r = 0; r < RPW; ++r) {
        int g = g0 + r;
        int ridx = rbin[(g < cnt) ? g : 0];
        const char* src = (const char*)(x + (size_t)ridx * DIN) + lane * 16;
        uint32_t dst = (uint32_t)__cvta_generic_to_shared(xb + r * DIN) + lane * 16;
        cpasync16(dst, src);
        cpasync16(dst + 512, src + 512);
    }
}

__global__ void __launch_bounds__(256, 1)
compute_kernel(const float* __restrict__ x, const float* __restrict__ W1,
               const float* __restrict__ W2, float* __restrict__ out, int n) {
    const int head = blockIdx.y;
    const int cnt  = g_counts[head];
    const int chunk_base = blockIdx.x * CHUNK;
    if (chunk_base >= cnt) return;
    const int binstart = g_offsets[head];

    extern __shared__ float smem[];
    float* w1t  = smem;                                   // [32][260]
    float* xall = smem + WSMEM;                           // 8 warps * 2 * 2048
    float* scr  = xall + WARPS * 2 * XBUF;                // 8 warps * 288
    float* w2s  = scr + WARPS * SCRW;                     // 128 floats

    const int tid  = threadIdx.x;
    const int warp = tid >> 5;
    const int lane = tid & 31;

    // ---- W1 head-block transposed (j-major, k contiguous) ----
    for (int idx = tid; idx < 32 * DIN; idx += 256) {
        int j = idx & 31;          // coalesced gmem in j
        int k = idx >> 5;
        w1t[j * WSTRIDE + k] = W1[k * DHID + head * 32 + j];
    }
    // ---- W2 head-block to smem ----
    if (tid < 128) w2s[tid] = W2[head * 32 * DOUT + tid];
    __syncthreads();

    float* xb0 = xall + warp * 2 * XBUF;
    float* xb1 = xb0 + XBUF;
    float* sb  = scr + warp * SCRW;
    const int* rbin = g_rowidx + binstart;

    const int o    = lane & 3;     // output channel for epilogue
    const int rsel = lane >> 2;    // row slot for epilogue

    const float S1 = 0.0625f;                 // 1/sqrt(256)
    const float S2 = 0.08838834764831845f;    // 1/sqrt(128)

    // ---- prefetch iter 0 ----
    {
        int g0 = chunk_base + warp * RPW;
        if (g0 < cnt) stage_rows(xb0, x, rbin, g0, cnt, lane);
        CP_COMMIT();
    }

    for (int it = 0; it < ITERS; ++it) {
        const int gcur = chunk_base + it * ROWS_ITER + warp * RPW;
        if (gcur >= cnt) { CP_WAIT_ALL(); break; }   // warp-uniform

        // ---- prefetch next iter into the other buffer ----
        const int gnext = gcur + ROWS_ITER;
        float* bufc = (it & 1) ? xb1 : xb0;
        float* bufn = (it & 1) ? xb0 : xb1;
        if (it + 1 < ITERS && gnext < cnt)
            stage_rows(bufn, x, rbin, gnext, cnt, lane);
        CP_COMMIT();
        CP_WAIT1();          // current buffer's group complete
        __syncwarp();        // cross-lane smem visibility

        // ---- main loop: 8 rows, lane = j, K-paired FFMA2 ----
        unsigned long long acc[RPW];
        #pragma unroll
        for (int r = 0; r < RPW; ++r) acc[r] = 0ULL;

        const ulonglong2* wp = reinterpret_cast<const ulonglong2*>(
                                   w1t + lane * WSTRIDE);
        const ulonglong2* xp = reinterpret_cast<const ulonglong2*>(bufc);

        #pragma unroll 2
        for (int k4 = 0; k4 < 64; ++k4) {
            ulonglong2 wv = wp[k4];                 // {w2k,w2k+1},{w2k+2,w2k+3}
            #pragma unroll
            for (int r = 0; r < RPW; ++r) {
                ulonglong2 xv = xp[r * 64 + k4];    // broadcast
                acc[r] = ffma2(wv.x, xv.x, acc[r]);
                acc[r] = ffma2(wv.y, xv.y, acc[r]);
            }
        }

        // ---- silu + transpose through smem ----
        #pragma unroll
        for (int r = 0; r < RPW; ++r) {
            float2 v = unpack2(acc[r]);
            float h = (v.x + v.y) * S1;
            h = __fdividef(h, 1.0f + __expf(-h));
            sb[lane * 9 + r] = h;                   // bank-conflict-free (9 odd)
        }
        __syncwarp();

        // ---- second matmul: lane = (row slot, out channel) ----
        float oacc = 0.f;
        #pragma unroll
        for (int j = 0; j < 32; ++j)
            oacc = fmaf(sb[j * 9 + rsel], w2s[j * 4 + o], oacc);

        int g = gcur + rsel;
        if (g < cnt)
            out[(size_t)rbin[g] * DOUT + o] = oacc * S2;
        __syncwarp();        // before sb is rewritten next iter
    }
}

// ============================================================
// launcher
// ============================================================
extern "C" void kernel_launch(void* const* d_in, const int* in_sizes, int n_in,
                              void* d_out, int out_size) {
    const float* x     = (const float*)d_in[0];
    const float* W1    = (const float*)d_in[1];
    const float* W2    = (const float*)d_in[2];
    const int*   heads = (const int*)d_in[3];
    float*       out   = (float*)d_out;

    int n = in_sizes[0] / DIN;
    if (n > NMAX) n = NMAX;
    if (n <= 0) return;

    static int attr_done = 0;   // host-side API config, not device work
    if (!attr_done) {
        cudaFuncSetAttribute(compute_kernel,
                             cudaFuncAttributeMaxDynamicSharedMemorySize,
                             SMEM_BYTES);
        attr_done = 1;
    }

    zero_kernel<<<1, 32>>>();
    int hist_blocks = (n + 1023) / 1024;
    hist_kernel<<<hist_blocks, 256>>>(heads, n);
    scan_kernel<<<1, 32>>>();
    scatter_kernel<<<hist_blocks, 256>>>(heads, n);

    dim3 grid((n + CHUNK - 1) / CHUNK, NHEADS);
    compute_kernel<<<grid, 256, SMEM_BYTES>>>(x, W1, W2, out, n);
}

// round 10
// speedup vs baseline: 2.7148x; 2.3659x over previous
#include <cuda_runtime.h>
#include <cuda_bf16.h>
#include <cstdint>

#define NMAX   500000
#define DIN    256
#define DHID   128
#define NHEADS 4
#define DOUT   4
#define REGION (NMAX / NHEADS + 8192)   // bin region with slack

// ---- persistent scratch (no allocations allowed) ----
__device__ int g_rowidx[NHEADS * REGION];
__device__ int g_cursor[NHEADS];

// ============================================================
// Pass 0: init bin cursors
// ============================================================
__global__ void zero_kernel() {
    int t = threadIdx.x;
    if (t < NHEADS) g_cursor[t] = t * REGION;
}

// ============================================================
// Pass 1: single-pass scatter, ballot-aggregated warp atomics
// ============================================================
__global__ void scatter_kernel(const int* __restrict__ heads, int n) {
    int lane = threadIdx.x & 31;
    int i0 = blockIdx.x * 1024 + threadIdx.x;
    #pragma unroll
    for (int u = 0; u < 4; ++u) {
        int i = i0 + u * 256;
        int h = (i < n) ? heads[i] : -1;
        #pragma unroll
        for (int hh = 0; hh < NHEADS; ++hh) {
            unsigned m = __ballot_sync(0xffffffffu, h == hh);
            if (m) {
                int leader = __ffs(m) - 1;
                int base = 0;
                if (lane == leader) base = atomicAdd(&g_cursor[hh], __popc(m));
                base = __shfl_sync(0xffffffffu, base, leader);
                if (h == hh)
                    g_rowidx[base + __popc(m & ((1u << lane) - 1))] = i;
            }
        }
    }
}

// ============================================================
// split fp32 pair -> bf16x2 hi + bf16x2 lo (packed, low half = .x)
// ============================================================
__device__ __forceinline__ void split2(float2 f, uint32_t& h, uint32_t& l) {
    asm("cvt.rn.bf16x2.f32 %0, %1, %2;" : "=r"(h) : "f"(f.y), "f"(f.x));
    float hx = __uint_as_float(h << 16);
    float hy = __uint_as_float(h & 0xffff0000u);
    asm("cvt.rn.bf16x2.f32 %0, %1, %2;" : "=r"(l) : "f"(f.y - hy), "f"(f.x - hx));
}

__device__ __forceinline__ void mma16816(float* c, const uint32_t* a,
                                         uint32_t b0, uint32_t b1) {
    asm volatile(
        "mma.sync.aligned.m16n8k16.row.col.f32.bf16.bf16.f32 "
        "{%0,%1,%2,%3}, {%4,%5,%6,%7}, {%8,%9}, {%0,%1,%2,%3};"
        : "+f"(c[0]), "+f"(c[1]), "+f"(c[2]), "+f"(c[3])
        : "r"(a[0]), "r"(a[1]), "r"(a[2]), "r"(a[3]), "r"(b0), "r"(b1));
}

// ============================================================
// Compute: CTA = 256 binned rows x head; 8 warps x 32 rows each.
//   A fragments gathered GMEM->regs (float2 per lane), split to bf16 hi/lo.
//   B = W1 head-block hi/lo in smem [n][k], stride 264 (conflict-free).
//   D = Ah*Bh + Ah*Bl + Al*Bh via mma.sync m16n8k16 (24 HMMA / K-step).
//   Epilogue: silu + W2 dot with butterfly reduce over the 4 c-lanes.
// ============================================================
#define BSTRIDE 264   // bf16 elements per B row (256 + 8 pad)

__global__ void __launch_bounds__(256, 2)
compute_kernel(const float* __restrict__ x, const float* __restrict__ W1,
               const float* __restrict__ W2, float* __restrict__ out) {
    const int head = blockIdx.y;
    const int binstart = head * REGION;
    const int cnt = g_cursor[head] - binstart;
    const int ctabase = blockIdx.x * 256;
    if (ctabase >= cnt) return;
    const int* rbin = g_rowidx + binstart;

    __shared__ __align__(16) unsigned short Bh[32 * BSTRIDE];
    __shared__ __align__(16) unsigned short Bl[32 * BSTRIDE];
    __shared__ float w2s[128];

    const int tid = threadIdx.x, warp = tid >> 5, lane = tid & 31;
    const int g = lane >> 2, c = lane & 3;

    // ---- B = W1 head block, split bf16 hi/lo ----
    #pragma unroll
    for (int i = 0; i < 32; ++i) {
        int el = tid + 256 * i;          // 8192 = 32 n * 256 k
        int nn = el & 31, k = el >> 5;   // coalesced gmem in nn
        float w = W1[k * DHID + head * 32 + nn];
        __nv_bfloat16 hb = __float2bfloat16_rn(w);
        float hf = __bfloat162float(hb);
        __nv_bfloat16 lb = __float2bfloat16_rn(w - hf);
        Bh[nn * BSTRIDE + k] = __bfloat16_as_ushort(hb);
        Bl[nn * BSTRIDE + k] = __bfloat16_as_ushort(lb);
    }
    if (tid < 128) w2s[tid] = W2[head * 128 + tid];
    __syncthreads();

    const int tb = ctabase + warp * 32;
    if (tb >= cnt) return;               // warps independent from here on

    // ---- this lane's 4 rows: g, g+8, g+16, g+24 within the 32-row tile ----
    int ridx[4];
    bool rv[4];
    const float* pr[4];
    #pragma unroll
    for (int rr = 0; rr < 4; ++rr) {
        int grow = tb + rr * 8 + g;
        rv[rr] = (grow < cnt);
        ridx[rr] = rbin[rv[rr] ? grow : (cnt - 1)];
        pr[rr] = x + (size_t)ridx[rr] * DIN + 2 * c;
    }
    // M-tile 0 = rows {g, g+8} (rr 0,1); M-tile 1 = rows {g+16, g+24} (rr 2,3)

    float acc[2][4][4];
    #pragma unroll
    for (int mt = 0; mt < 2; ++mt)
        #pragma unroll
        for (int nt = 0; nt < 4; ++nt)
            #pragma unroll
            for (int q = 0; q < 4; ++q) acc[mt][nt][q] = 0.f;

    // ---- prefetch K-step 0 ----
    float2 fa[4], fb[4], na[4], nb[4];
    #pragma unroll
    for (int rr = 0; rr < 4; ++rr) {
        fa[rr] = *(const float2*)(pr[rr]);
        fb[rr] = *(const float2*)(pr[rr] + 8);
    }

    #pragma unroll
    for (int ks = 0; ks < 16; ++ks) {
        // prefetch next K-step while computing this one
        if (ks < 15) {
            #pragma unroll
            for (int rr = 0; rr < 4; ++rr) {
                na[rr] = *(const float2*)(pr[rr] + (ks + 1) * 16);
                nb[rr] = *(const float2*)(pr[rr] + (ks + 1) * 16 + 8);
            }
        }

        // convert to fragments: a0=(g,k2c) a1=(g+8,k2c) a2=(g,k+8) a3=(g+8,k+8)
        uint32_t Ah[2][4], Al[2][4];
        #pragma unroll
        for (int mt = 0; mt < 2; ++mt) {
            split2(fa[mt * 2 + 0], Ah[mt][0], Al[mt][0]);
            split2(fa[mt * 2 + 1], Ah[mt][1], Al[mt][1]);
            split2(fb[mt * 2 + 0], Ah[mt][2], Al[mt][2]);
            split2(fb[mt * 2 + 1], Ah[mt][3], Al[mt][3]);
        }

        #pragma unroll
        for (int nt = 0; nt < 4; ++nt) {
            int be = (nt * 8 + g) * BSTRIDE + ks * 16 + 2 * c;
            uint32_t bh0 = *(const uint32_t*)(Bh + be);
            uint32_t bh1 = *(const uint32_t*)(Bh + be + 8);
            uint32_t bl0 = *(const uint32_t*)(Bl + be);
            uint32_t bl1 = *(const uint32_t*)(Bl + be + 8);
            #pragma unroll
            for (int mt = 0; mt < 2; ++mt) {
                mma16816(acc[mt][nt], Ah[mt], bh0, bh1);
                mma16816(acc[mt][nt], Ah[mt], bl0, bl1);
                mma16816(acc[mt][nt], Al[mt], bh0, bh1);
            }
        }

        #pragma unroll
        for (int rr = 0; rr < 4; ++rr) { fa[rr] = na[rr]; fb[rr] = nb[rr]; }
    }

    // ---- epilogue: silu + W2, butterfly over c-lanes, store float4 ----
    const float S1 = 0.0625f;               // 1/sqrt(256)
    const float S2 = 0.08838834764831845f;  // 1/sqrt(128)

    #pragma unroll
    for (int rr = 0; rr < 4; ++rr) {
        int mt = rr >> 1, q0 = (rr & 1) * 2;
        float p0 = 0.f, p1 = 0.f, p2 = 0.f, p3 = 0.f;
        #pragma unroll
        for (int nt = 0; nt < 4; ++nt) {
            #pragma unroll
            for (int e = 0; e < 2; ++e) {
                int j = nt * 8 + 2 * c + e;
                float h = acc[mt][nt][q0 + e] * S1;
                h = __fdividef(h, 1.0f + __expf(-h));
                p0 = fmaf(h, w2s[j * 4 + 0], p0);
                p1 = fmaf(h, w2s[j * 4 + 1], p1);
                p2 = fmaf(h, w2s[j * 4 + 2], p2);
                p3 = fmaf(h, w2s[j * 4 + 3], p3);
            }
        }
        #pragma unroll
        for (int d = 1; d <= 2; d <<= 1) {
            p0 += __shfl_xor_sync(0xffffffffu, p0, d);
            p1 += __shfl_xor_sync(0xffffffffu, p1, d);
            p2 += __shfl_xor_sync(0xffffffffu, p2, d);
            p3 += __shfl_xor_sync(0xffffffffu, p3, d);
        }
        if (c == 0 && rv[rr]) {
            *(float4*)(out + (size_t)ridx[rr] * DOUT) =
                make_float4(p0 * S2, p1 * S2, p2 * S2, p3 * S2);
        }
    }
}

// ============================================================
// launcher
// ============================================================
extern "C" void kernel_launch(void* const* d_in, const int* in_sizes, int n_in,
                              void* d_out, int out_size) {
    const float* x     = (const float*)d_in[0];
    const float* W1    = (const float*)d_in[1];
    const float* W2    = (const float*)d_in[2];
    const int*   heads = (const int*)d_in[3];
    float*       out   = (float*)d_out;

    int n = in_sizes[0] / DIN;
    if (n > NMAX) n = NMAX;
    if (n <= 0) return;

    zero_kernel<<<1, 32>>>();
    scatter_kernel<<<(n + 1023) / 1024, 256>>>(heads, n);

    int gx = (REGION + 255) / 256;      // covers worst-case head bin
    dim3 grid(gx, NHEADS);
    compute_kernel<<<grid, 256>>>(x, W1, W2, out);
}